// round 9
// baseline (speedup 1.0000x reference)
#include <cuda_runtime.h>

// QConv1d, conjugation closed form; 4 co per thread (two f32x2 co-pairs),
// 512-thread blocks: 32 t x 16 ci-groups (one ci each), smem reduction.
// x: (B, CIN, T, 4)   a,b,c: (COUT, CIN, FL)   out: (B, COUT, TOUT, 4)

#define B_    2
#define CIN_  16
#define COUT_ 16
#define T_    2048
#define FL_   9
#define TOUT_ 2040
#define NQ    4        // co per thread (2 packed pairs)

typedef unsigned long long ull;

__device__ __forceinline__ ull pk2(float lo, float hi) {
    ull r; asm("mov.b64 %0,{%1,%2};" : "=l"(r)
               : "r"(__float_as_uint(lo)), "r"(__float_as_uint(hi)));
    return r;
}
__device__ __forceinline__ void upk2(ull v, float& lo, float& hi) {
    unsigned a, b; asm("mov.b64 {%0,%1},%2;" : "=r"(a), "=r"(b) : "l"(v));
    lo = __uint_as_float(a); hi = __uint_as_float(b);
}
__device__ __forceinline__ ull bc2(float v) { return pk2(v, v); }
__device__ __forceinline__ ull f2(ull a, ull b, ull c) {
    ull r; asm("fma.rn.f32x2 %0,%1,%2,%3;" : "=l"(r) : "l"(a), "l"(b), "l"(c));
    return r;
}
__device__ __forceinline__ ull m2(ull a, ull b) {
    ull r; asm("mul.rn.f32x2 %0,%1,%2;" : "=l"(r) : "l"(a), "l"(b));
    return r;
}
__device__ __forceinline__ ull a2_(ull a, ull b) {
    ull r; asm("add.rn.f32x2 %0,%1,%2;" : "=l"(r) : "l"(a), "l"(b));
    return r;
}
__device__ __forceinline__ float rcpf(float x) {
    float r; asm("rcp.approx.f32 %0,%1;" : "=f"(r) : "f"(x));
    return r;
}
__device__ __forceinline__ ull rcp2(ull v) {
    float lo, hi; upk2(v, lo, hi);
    return pk2(rcpf(lo), rcpf(hi));
}

__global__ __launch_bounds__(32 * CIN_)
void qconv1d_kernel(const float* __restrict__ x,
                    const float* __restrict__ pa,
                    const float* __restrict__ pb,
                    const float* __restrict__ pc,
                    float* __restrict__ out)
{
    __shared__ ull sp[CIN_][FL_][3][2];          // {a,b,c} x {pair0,pair1}
    __shared__ ull red[CIN_ - 1][32][2][4];

    const int tx  = threadIdx.x;
    const int ci  = threadIdx.y;                 // 0..15, one ci per group
    const int tid = ci * 32 + tx;
    const int t   = blockIdx.x * 32 + tx;
    const int co0 = blockIdx.y * NQ;
    const int b   = blockIdx.z;
    const int tL  = t < TOUT_ ? t : (TOUT_ - 1);

    // pack params: 16*9*3*2 = 864 packed entries, 512 threads
    for (int e2 = tid; e2 < CIN_ * FL_ * 3 * 2; e2 += 32 * CIN_) {
        const int j   = e2 & 1;
        const int e   = e2 >> 1;
        const int prm = e % 3;
        const int f   = (e / 3) % FL_;
        const int cci = e / (3 * FL_);
        const int s0 = ((co0 + 2 * j) * CIN_ + cci) * FL_ + f;
        const int s1 = s0 + CIN_ * FL_;
        const float* P = (prm == 0) ? pa : (prm == 1) ? pb : pc;
        sp[cci][f][prm][j] = pk2(__ldg(P + s0), __ldg(P + s1));
    }
    __syncthreads();

    const float4* xr = reinterpret_cast<const float4*>(x)
                     + ((size_t)b * CIN_ + ci) * T_ + tL;

    // center tap qp: packed broadcasts made once
    const float4 v4 = __ldg(xr + 4);
    const ull pw2  = bc2(v4.x);
    const ull vx2  = bc2(v4.y);
    const ull vy2  = bc2(v4.z);
    const ull vz2  = bc2(v4.w);
    const float vsq = v4.y*v4.y + v4.z*v4.z + v4.w*v4.w;
    const ull vsq2  = bc2(vsq);
    const ull nvsq2 = bc2(-vsq);

    ull aw[2], ax[2], ay[2], az[2];
    #pragma unroll
    for (int j = 0; j < 2; ++j) { aw[j]=0; ax[j]=0; ay[j]=0; az[j]=0; }

    #pragma unroll
    for (int f = 0; f < FL_; ++f) {
        const float4 u4 = __ldg(xr + f);
        // broadcasts of u (and negations, reused twice each in the body)
        const ull s2   = bc2(u4.x);
        const ull ux2  = bc2(u4.y);
        const ull uy2  = bc2(u4.z);
        const ull uz2  = bc2(u4.w);
        const ull nux2 = bc2(-u4.y);
        const ull nuy2 = bc2(-u4.z);
        const ull nuz2 = bc2(-u4.w);

        // packed co-invariants: R(w) = w^2 u + w (2 v x u) + (2d v - vsq u)
        ull d2 = f2(vx2, ux2, f2(vy2, uy2, m2(vz2, uz2)));
        d2 = a2_(d2, d2);
        ull crx = f2(vy2, uz2, m2(vz2, nuy2)); crx = a2_(crx, crx);
        ull cry = f2(vz2, ux2, m2(vx2, nuz2)); cry = a2_(cry, cry);
        ull crz = f2(vx2, uy2, m2(vy2, nux2)); crz = a2_(crz, crz);
        const ull a0x = f2(d2, vx2, m2(nvsq2, ux2));
        const ull a0y = f2(d2, vy2, m2(nvsq2, uy2));
        const ull a0z = f2(d2, vz2, m2(nvsq2, uz2));

        #pragma unroll
        for (int j = 0; j < 2; ++j) {
            const ull A2 = sp[ci][f][0][j];
            const ull B2 = sp[ci][f][1][j];
            const ull C2 = sp[ci][f][2][j];

            const ull w2   = a2_(pw2, C2);
            const ull nsq2 = f2(w2, w2, vsq2);
            const ull rn2  = rcp2(nsq2);
            const ull arn2 = m2(A2, rn2);

            const ull Rx = m2(f2(w2, f2(w2, ux2, crx), a0x), arn2);
            const ull Ry = m2(f2(w2, f2(w2, uy2, cry), a0y), arn2);
            const ull Rz = m2(f2(w2, f2(w2, uz2, crz), a0z), arn2);
            const ull Rw = m2(s2, A2);
            const ull qw2 = a2_(s2, B2);

            // acc += (q + b e) (x) R  — negatives via pre-negated u broadcasts
            aw[j] = f2(qw2, Rw, aw[j]);
            aw[j] = f2(nux2, Rx, aw[j]);
            aw[j] = f2(nuy2, Ry, aw[j]);
            aw[j] = f2(nuz2, Rz, aw[j]);
            ax[j] = f2(qw2, Rx, ax[j]);
            ax[j] = f2(ux2, Rw, ax[j]);
            ax[j] = f2(uy2, Rz, ax[j]);
            ax[j] = f2(nuz2, Ry, ax[j]);
            ay[j] = f2(qw2, Ry, ay[j]);
            ay[j] = f2(nux2, Rz, ay[j]);
            ay[j] = f2(uy2, Rw, ay[j]);
            ay[j] = f2(uz2, Rx, ay[j]);
            az[j] = f2(qw2, Rz, az[j]);
            az[j] = f2(ux2, Ry, az[j]);
            az[j] = f2(nuy2, Rx, az[j]);
            az[j] = f2(uz2, Rw, az[j]);
        }
    }

    // flat reduction over the 16 ci groups
    if (ci > 0) {
        #pragma unroll
        for (int j = 0; j < 2; ++j) {
            red[ci - 1][tx][j][0] = aw[j];
            red[ci - 1][tx][j][1] = ax[j];
            red[ci - 1][tx][j][2] = ay[j];
            red[ci - 1][tx][j][3] = az[j];
        }
    }
    __syncthreads();
    if (ci == 0 && t < TOUT_) {
        #pragma unroll
        for (int j = 0; j < 2; ++j) {
            ull w = aw[j], X = ax[j], Y = ay[j], Z = az[j];
            #pragma unroll
            for (int k = 0; k < CIN_ - 1; ++k) {
                w = a2_(w, red[k][tx][j][0]);
                X = a2_(X, red[k][tx][j][1]);
                Y = a2_(Y, red[k][tx][j][2]);
                Z = a2_(Z, red[k][tx][j][3]);
            }
            float w0, w1, x0, x1, y0, y1, z0, z1;
            upk2(w, w0, w1); upk2(X, x0, x1); upk2(Y, y0, y1); upk2(Z, z0, z1);
            float4* o4 = reinterpret_cast<float4*>(out)
                       + (size_t)b * COUT_ * TOUT_ + t;
            o4[(size_t)(co0 + 2*j + 0) * TOUT_] = make_float4(w0, x0, y0, z0);
            o4[(size_t)(co0 + 2*j + 1) * TOUT_] = make_float4(w1, x1, y1, z1);
        }
    }
}

extern "C" void kernel_launch(void* const* d_in, const int* in_sizes, int n_in,
                              void* d_out, int out_size)
{
    const float* x  = (const float*)d_in[0];
    const float* pa = (const float*)d_in[1];
    const float* pb = (const float*)d_in[2];
    const float* pc = (const float*)d_in[3];
    float* out = (float*)d_out;

    dim3 block(32, CIN_, 1);
    dim3 grid((TOUT_ + 31) / 32, COUT_ / NQ, B_);
    qconv1d_kernel<<<grid, block>>>(x, pa, pb, pc, out);
}